// round 1
// baseline (speedup 1.0000x reference)
#include <cuda_runtime.h>

// ---------------- problem constants ----------------
constexpr int B = 16, C = 64, H = 128, W = 128, O = 128, KE = 9;
constexpr int O_TILE = 64;   // output channels per block
constexpr int H_T = 4;       // output rows per block
constexpr int W_T = 64;      // output cols per block
constexpr int CCH = 8;       // input channels staged per smem round
constexpr int XROW = 66;     // x smem row stride (66 mod 32 = 2 -> only 2-way conflicts)

// weight scratch, transposed to [c][k][o] for coalesced smem fills
__device__ float g_wt[C * KE * O];

// ---------------- f32x2 helpers ----------------
__device__ __forceinline__ unsigned long long pack2(float v) {
    unsigned long long r;
    asm("mov.b64 %0, {%1, %1};" : "=l"(r) : "f"(v));
    return r;
}

#define FFMA2(d, a, bb, c) \
    asm("fma.rn.f32x2 %0, %1, %2, %3;" : "=l"(d) : "l"(a), "l"(bb), "l"(c))

// ---------------- prep: transpose weights [o][c][k] -> [c][k][o] ----------------
__global__ void wt_transpose_kernel(const float* __restrict__ w) {
    int idx = blockIdx.x * 256 + threadIdx.x;
    if (idx < O * C * KE) {
        int o = idx / (C * KE);
        int rem = idx % (C * KE);
        int c = rem / KE;
        int k = rem % KE;
        g_wt[(c * KE + k) * O + o] = w[idx];
    }
}

// ---------------- main conv ----------------
__global__ __launch_bounds__(256, 2)
void conv3x3_kernel(const float* __restrict__ x, float* __restrict__ out) {
    __shared__ __align__(16) float xs[CCH][6][XROW];       // 8c x (4+2) rows x 66 cols
    __shared__ __align__(16) float ws[CCH][KE][O_TILE];    // 8c x 9 taps x 64 o

    const int tid = threadIdx.x;
    const int og  = tid >> 5;        // o-group (warp-uniform -> broadcast weight LDS)
    const int sp  = tid & 31;
    const int r   = sp >> 3;         // row within 4-row tile
    const int cg  = sp & 7;          // col-group (8 cols each)

    const int b  = blockIdx.z;
    const int o0 = blockIdx.y * O_TILE;
    const int h0 = (blockIdx.x >> 1) * H_T;
    const int w0 = (blockIdx.x & 1) * W_T;

    unsigned long long acc[4][8];
    #pragma unroll
    for (int p = 0; p < 4; p++)
        #pragma unroll
        for (int j = 0; j < 8; j++)
            acc[p][j] = 0ull;

    const float* xb = x + (size_t)b * C * H * W;

    for (int cc = 0; cc < C; cc += CCH) {
        __syncthreads();

        // ---- stage x tile: [CCH][6][66] with zero halo ----
        for (int idx = tid; idx < CCH * 6 * 66; idx += 256) {
            int ci  = idx / (6 * 66);
            int rem = idx % (6 * 66);
            int rr  = rem / 66;
            int ww  = rem % 66;
            int gh = h0 - 1 + rr;
            int gw = w0 - 1 + ww;
            float v = 0.0f;
            if ((unsigned)gh < (unsigned)H && (unsigned)gw < (unsigned)W)
                v = xb[(size_t)(cc + ci) * (H * W) + gh * W + gw];
            xs[ci][rr][ww] = v;
        }
        // ---- stage weights: coalesced rows of 64 from g_wt[c][k][o] ----
        for (int idx = tid; idx < CCH * KE * O_TILE; idx += 256) {
            int ci  = idx / (KE * O_TILE);
            int rem = idx % (KE * O_TILE);
            int k   = rem / O_TILE;
            int oo  = rem % O_TILE;
            ws[ci][k][oo] = g_wt[((cc + ci) * KE + k) * O + o0 + oo];
        }
        __syncthreads();

        #pragma unroll 1
        for (int ci = 0; ci < CCH; ci++) {
            #pragma unroll
            for (int dh = 0; dh < 3; dh++) {
                // 10 consecutive x values cover all three dw shifts for 8 cols
                unsigned long long xp[10];
                #pragma unroll
                for (int i = 0; i < 10; i++)
                    xp[i] = pack2(xs[ci][r + dh][cg * 8 + i]);

                #pragma unroll
                for (int dw = 0; dw < 3; dw++) {
                    const int k = dh * 3 + dw;
                    #pragma unroll
                    for (int p = 0; p < 4; p++) {
                        // warp-uniform address -> broadcast LDS.64 (o, o+1)
                        unsigned long long w2 =
                            *(const unsigned long long*)&ws[ci][k][og * 8 + p * 2];
                        #pragma unroll
                        for (int j = 0; j < 8; j++)
                            FFMA2(acc[p][j], xp[dw + j], w2, acc[p][j]);
                    }
                }
            }
        }
    }

    // ---- store: unpack f32x2 pairs (o, o+1) ----
    const int h     = h0 + r;
    const int wbase = w0 + cg * 8;
    #pragma unroll
    for (int p = 0; p < 4; p++) {
        const int o = o0 + og * 8 + p * 2;
        float* op0 = out + (((size_t)b * O + o) * H + h) * W + wbase;
        float* op1 = op0 + (size_t)H * W;
        #pragma unroll
        for (int j = 0; j < 8; j++) {
            float lo, hi;
            asm("mov.b64 {%0, %1}, %2;" : "=f"(lo), "=f"(hi) : "l"(acc[p][j]));
            op0[j] = lo;
            op1[j] = hi;
        }
    }
}

// ---------------- launch ----------------
extern "C" void kernel_launch(void* const* d_in, const int* in_sizes, int n_in,
                              void* d_out, int out_size) {
    const float* x = (const float*)d_in[0];
    const float* w = (const float*)d_in[1];
    float* out = (float*)d_out;

    wt_transpose_kernel<<<(O * C * KE + 255) / 256, 256>>>(w);

    dim3 grid(/*h,w blocks*/ (H / H_T) * (W / W_T), O / O_TILE, B);  // 64, 2, 16
    conv3x3_kernel<<<grid, 256>>>(x, out);
}

// round 5
// speedup vs baseline: 2.0455x; 2.0455x over previous
#include <cuda_runtime.h>
#include <cuda_bf16.h>
#include <cstdint>

// ---------------- problem constants ----------------
constexpr int B_ = 16, C_ = 64, H_ = 128, W_ = 128, O_ = 128, KE_ = 9;
constexpr int HP = H_ + 2, WP = W_ + 2;   // padded x copy dims

// ---------------- device scratch (zero-initialized; halo rows/cols stay 0) ----
__device__ __align__(16) __nv_bfloat16 g_xhi[(size_t)B_ * HP * WP * C_];
__device__ __align__(16) __nv_bfloat16 g_xlo[(size_t)B_ * HP * WP * C_];
__device__ __align__(16) __nv_bfloat16 g_whi[KE_ * O_ * C_];
__device__ __align__(16) __nv_bfloat16 g_wlo[KE_ * O_ * C_];

// ---------------- smem layout (bytes) ----------------
// x tiles: [s=hi/lo][3 padded rows][130 cols] rows of 128B (c=64 bf16), SW128
constexpr int XROWS = 3 * 130;                  // 390
constexpr int XTILE = XROWS * 128;              // 49920 (128B-aligned)
constexpr int WS_OFF = 2 * XTILE;               // 99840
// w tile (per dh): [dw*2+s][o=128] rows of 128B
constexpr int WROWS = 6 * 128;                  // 768
constexpr int SMEM_TOTAL = WS_OFF + WROWS * 128;  // 198144

__device__ __forceinline__ uint32_t sw(uint32_t off) { return off ^ ((off >> 3) & 0x70); }

__device__ __forceinline__ uint32_t smem_u32(const void* p) {
    uint32_t a;
    asm("{ .reg .u64 t; cvta.to.shared.u64 t, %1; cvt.u32.u64 %0, t; }" : "=r"(a) : "l"(p));
    return a;
}

__device__ __forceinline__ void ldsm4(uint32_t* r, uint32_t addr) {
    asm volatile("ldmatrix.sync.aligned.m8n8.x4.shared.b16 {%0,%1,%2,%3}, [%4];"
                 : "=r"(r[0]), "=r"(r[1]), "=r"(r[2]), "=r"(r[3]) : "r"(addr));
}

__device__ __forceinline__ void mma16816(float* d, const uint32_t* a, const uint32_t* b) {
    asm volatile(
        "mma.sync.aligned.m16n8k16.row.col.f32.bf16.bf16.f32 "
        "{%0,%1,%2,%3}, {%4,%5,%6,%7}, {%8,%9}, {%0,%1,%2,%3};"
        : "+f"(d[0]), "+f"(d[1]), "+f"(d[2]), "+f"(d[3])
        : "r"(a[0]), "r"(a[1]), "r"(a[2]), "r"(a[3]), "r"(b[0]), "r"(b[1]));
}

// ---------------- prep: x -> transposed, padded, bf16 hi/lo ----------------
__global__ void prep_x(const float* __restrict__ x) {
    int idx = blockIdx.x * 256 + threadIdx.x;      // B*H*W threads
    int w = idx & (W_ - 1);
    int h = (idx >> 7) & (H_ - 1);
    int b = idx >> 14;
    const float* src = x + ((size_t)b * C_ * H_ + h) * W_ + w;
    size_t drow = ((size_t)(b * HP + h + 1) * WP + (w + 1)) * C_;
    #pragma unroll
    for (int cb = 0; cb < 8; cb++) {
        __align__(16) __nv_bfloat16 hv[8], lv[8];
        #pragma unroll
        for (int j = 0; j < 8; j++) {
            float v = src[(size_t)(cb * 8 + j) * H_ * W_];
            __nv_bfloat16 hi = __float2bfloat16(v);
            hv[j] = hi;
            lv[j] = __float2bfloat16(v - __bfloat162float(hi));
        }
        *(uint4*)(g_xhi + drow + cb * 8) = *(const uint4*)hv;
        *(uint4*)(g_xlo + drow + cb * 8) = *(const uint4*)lv;
    }
}

// ---------------- prep: weights [o][c][k] -> [k][o][c] bf16 hi/lo ----------------
__global__ void prep_w(const float* __restrict__ w) {
    int idx = blockIdx.x * 256 + threadIdx.x;      // KE*O*C
    int c = idx & 63;
    int o = (idx >> 6) & 127;
    int k = idx >> 13;
    float v = w[(o * C_ + c) * KE_ + k];
    __nv_bfloat16 hi = __float2bfloat16(v);
    g_whi[idx] = hi;
    g_wlo[idx] = __float2bfloat16(v - __bfloat162float(hi));
}

// ---------------- main conv: warp-level mma.sync implicit GEMM ----------------
__global__ __launch_bounds__(256, 1)
void conv_mma_kernel(float* __restrict__ out) {
    extern __shared__ char smem[];
    char* sm = smem;
    const uint32_t sbase = smem_u32(smem);
    const int tid = threadIdx.x;
    const int l = tid & 31, wid = tid >> 5;
    const int warpM = (wid >> 1) * 32;   // o offset: 0,32,64,96
    const int warpN = (wid & 1) * 64;    // w offset: 0,64
    const int h0 = blockIdx.x, b = blockIdx.y;

    // per-lane ldmatrix row/col pieces
    const int arow  = (l & 7) + ((l >> 3) & 1) * 8;   // A: mats (0,0),(8,0),(0,8),(8,8)
    const int acolb = ((l >> 4) & 1) * 16;
    const int brow  = (l & 7) + ((l >> 4) & 1) * 8;   // B: mats (n0,k0),(n0,k8),(n8,k0),(n8,k8)
    const int bcolb = ((l >> 3) & 1) * 16;

    // ---- stage x rows h0..h0+2 (padded coords), hi + lo ----
    for (int idx = tid; idx < 2 * XROWS * 8; idx += 256) {
        int s = idx >= XROWS * 8;
        int rem = idx - s * (XROWS * 8);
        int row = rem >> 3, chunk = rem & 7;
        int r = row / 130, wc = row - r * 130;
        const __nv_bfloat16* src = (s ? g_xlo : g_xhi)
            + ((size_t)(b * HP + h0 + r) * WP + wc) * C_ + chunk * 8;
        *(uint4*)(sm + s * XTILE + sw(row * 128 + chunk * 16)) = *(const uint4*)src;
    }

    float acc[2][8][4];
    #pragma unroll
    for (int mt = 0; mt < 2; mt++)
        #pragma unroll
        for (int nt = 0; nt < 8; nt++)
            #pragma unroll
            for (int q = 0; q < 4; q++) acc[mt][nt][q] = 0.0f;

    #pragma unroll 1
    for (int dh = 0; dh < 3; dh++) {
        __syncthreads();   // previous dh's readers done before W overwrite
        // ---- stage w tiles for this dh: [dw][s][o][c] ----
        for (int idx = tid; idx < WROWS * 8; idx += 256) {
            int row = idx >> 3, chunk = idx & 7;
            int dws = row >> 7, o = row & 127;
            int dw = dws >> 1, s = dws & 1;
            const __nv_bfloat16* src = (s ? g_wlo : g_whi)
                + ((size_t)((dh * 3 + dw) * O_ + o)) * C_ + chunk * 8;
            *(uint4*)(sm + WS_OFF + sw(row * 128 + chunk * 16)) = *(const uint4*)src;
        }
        __syncthreads();

        #pragma unroll
        for (int dw = 0; dw < 3; dw++) {
            #pragma unroll
            for (int ks = 0; ks < 4; ks++) {
                uint32_t ah[2][4], al[2][4], bb[4][4];
                #pragma unroll
                for (int mt = 0; mt < 2; mt++) {
                    uint32_t rh = (uint32_t)((dw * 2) * 128 + warpM + mt * 16 + arow);
                    ldsm4(ah[mt], sbase + WS_OFF + sw(rh * 128 + ks * 32 + acolb));
                    uint32_t rl = rh + 128;    // s=1 tile is next 128 rows
                    ldsm4(al[mt], sbase + WS_OFF + sw(rl * 128 + ks * 32 + acolb));
                }
                // B from x_hi
                #pragma unroll
                for (int np = 0; np < 4; np++) {
                    uint32_t rn = (uint32_t)(dh * 130 + warpN + np * 16 + brow + dw);
                    ldsm4(bb[np], sbase + sw(rn * 128 + ks * 32 + bcolb));
                }
                #pragma unroll
                for (int mt = 0; mt < 2; mt++)
                    #pragma unroll
                    for (int np = 0; np < 4; np++) {
                        mma16816(acc[mt][2 * np],     ah[mt], &bb[np][0]);  // w_hi * x_hi
                        mma16816(acc[mt][2 * np + 1], ah[mt], &bb[np][2]);
                        mma16816(acc[mt][2 * np],     al[mt], &bb[np][0]);  // w_lo * x_hi
                        mma16816(acc[mt][2 * np + 1], al[mt], &bb[np][2]);
                    }
                // B from x_lo
                #pragma unroll
                for (int np = 0; np < 4; np++) {
                    uint32_t rn = (uint32_t)(dh * 130 + warpN + np * 16 + brow + dw);
                    ldsm4(bb[np], sbase + XTILE + sw(rn * 128 + ks * 32 + bcolb));
                }
                #pragma unroll
                for (int mt = 0; mt < 2; mt++)
                    #pragma unroll
                    for (int np = 0; np < 4; np++) {
                        mma16816(acc[mt][2 * np],     ah[mt], &bb[np][0]);  // w_hi * x_lo
                        mma16816(acc[mt][2 * np + 1], ah[mt], &bb[np][2]);
                    }
            }
        }
    }

    // ---- epilogue: fragment -> out[b][o][h0][w], coalesced float2 stores ----
    const int gid = l >> 2, tg = l & 3;
    #pragma unroll
    for (int mt = 0; mt < 2; mt++)
        #pragma unroll
        for (int half = 0; half < 2; half++) {
            int o = warpM + mt * 16 + gid + half * 8;
            float* dst = out + (((size_t)b * O_ + o) * H_ + h0) * W_ + warpN + 2 * tg;
            #pragma unroll
            for (int nt = 0; nt < 8; nt++) {
                float2 v = make_float2(acc[mt][nt][half * 2], acc[mt][nt][half * 2 + 1]);
                *(float2*)(dst + nt * 8) = v;
            }
        }
}

// ---------------- launch ----------------
extern "C" void kernel_launch(void* const* d_in, const int* in_sizes, int n_in,
                              void* d_out, int out_size) {
    const float* x = (const float*)d_in[0];
    const float* w = (const float*)d_in[1];
    float* out = (float*)d_out;

    cudaFuncSetAttribute(conv_mma_kernel, cudaFuncAttributeMaxDynamicSharedMemorySize,
                         SMEM_TOTAL);

    prep_x<<<(B_ * H_ * W_) / 256, 256>>>(x);
    prep_w<<<(KE_ * O_ * C_) / 256, 256>>>(w);
    conv_mma_kernel<<<dim3(H_, B_), 256, SMEM_TOTAL>>>(out);
}

// round 6
// speedup vs baseline: 2.6898x; 1.3150x over previous
#include <cuda_runtime.h>
#include <cuda_bf16.h>
#include <cstdint>

// ---------------- problem constants ----------------
constexpr int B_ = 16, C_ = 64, H_ = 128, W_ = 128, O_ = 128, KE_ = 9;
constexpr int HP = H_ + 2, WP = W_ + 2;   // padded x copy dims

// ---------------- device scratch (zero-initialized; halo rows/cols stay 0) ----
__device__ __align__(16) __nv_bfloat16 g_xhi[(size_t)B_ * HP * WP * C_];
__device__ __align__(16) __nv_bfloat16 g_xlo[(size_t)B_ * HP * WP * C_];
__device__ __align__(16) __nv_bfloat16 g_whi[KE_ * O_ * C_];
__device__ __align__(16) __nv_bfloat16 g_wlo[KE_ * O_ * C_];

// ---------------- smem layout (bytes) ----------------
// x tiles: [s=hi/lo][3 padded rows][130 cols] rows of 128B (c=64 bf16), SW128
constexpr int XROWS = 3 * 130;                   // 390
constexpr int XTILE = XROWS * 128;               // 49920
constexpr int WS_OFF = 2 * XTILE;                // 99840
// w tile per (dh,dw): [s=hi/lo][o=128] rows of 128B = 32KB, double buffered
constexpr int WTILE = 256 * 128;                 // 32768
constexpr int SMEM_TOTAL = WS_OFF + 2 * WTILE;   // 165376

__device__ __forceinline__ uint32_t sw(uint32_t off) { return off ^ ((off >> 3) & 0x70); }

__device__ __forceinline__ uint32_t smem_u32(const void* p) {
    uint32_t a;
    asm("{ .reg .u64 t; cvta.to.shared.u64 t, %1; cvt.u32.u64 %0, t; }" : "=r"(a) : "l"(p));
    return a;
}

__device__ __forceinline__ void cp16(uint32_t dst, const void* src) {
    asm volatile("cp.async.cg.shared.global [%0], [%1], 16;" :: "r"(dst), "l"(src));
}
#define CP_COMMIT() asm volatile("cp.async.commit_group;" ::: "memory")
#define CP_WAIT(n)  asm volatile("cp.async.wait_group %0;" :: "n"(n) : "memory")

__device__ __forceinline__ void ldsm4(uint32_t* r, uint32_t addr) {
    asm volatile("ldmatrix.sync.aligned.m8n8.x4.shared.b16 {%0,%1,%2,%3}, [%4];"
                 : "=r"(r[0]), "=r"(r[1]), "=r"(r[2]), "=r"(r[3]) : "r"(addr));
}

__device__ __forceinline__ void mma16816(float* d, const uint32_t* a, const uint32_t* b) {
    asm volatile(
        "mma.sync.aligned.m16n8k16.row.col.f32.bf16.bf16.f32 "
        "{%0,%1,%2,%3}, {%4,%5,%6,%7}, {%8,%9}, {%0,%1,%2,%3};"
        : "+f"(d[0]), "+f"(d[1]), "+f"(d[2]), "+f"(d[3])
        : "r"(a[0]), "r"(a[1]), "r"(a[2]), "r"(a[3]), "r"(b[0]), "r"(b[1]));
}

// ---------------- prep: x -> padded NHWC bf16 hi/lo, coalesced via smem transpose --
// Block: (b, h, 32 w-cols) x all 64 c. Phase 1: coalesced 128B gmem reads, smem
// transpose. Phase 2: fully coalesced 128B row writes of the c-contiguous layout.
__global__ __launch_bounds__(256, 4) void prep_x(const float* __restrict__ x) {
    __shared__ __nv_bfloat16 sh_hi[32][72];   // [w][c], stride 72 (16B-aligned rows)
    __shared__ __nv_bfloat16 sh_lo[32][72];

    const int tid = threadIdx.x;
    const int wd = tid >> 5, l = tid & 31;
    const int blk = blockIdx.x;                  // b*H*4 + h*4 + wq
    const int wq = blk & 3;
    const int h  = (blk >> 2) & (H_ - 1);
    const int b  = blk >> 9;
    const int w0 = wq * 32;

    // phase 1: warp wd reads c rows {wd, wd+8, ..., wd+56}, 32 consecutive w each
    const float* src = x + (((size_t)b * C_ + wd) * H_ + h) * W_ + w0 + l;
    #pragma unroll
    for (int i = 0; i < 8; i++) {
        float v = src[(size_t)(i * 8) * H_ * W_];
        __nv_bfloat16 hi = __float2bfloat16(v);
        sh_hi[l][wd + i * 8] = hi;
        sh_lo[l][wd + i * 8] = __float2bfloat16(v - __bfloat162float(hi));
    }
    __syncthreads();

    // phase 2: thread = (pos, chunk); 8 consecutive threads write one 128B row
    const int pos = tid >> 3, chunk = tid & 7;
    size_t drow = ((size_t)(b * HP + h + 1) * WP + (w0 + pos + 1)) * C_ + chunk * 8;
    *(uint4*)(g_xhi + drow) = *(const uint4*)&sh_hi[pos][chunk * 8];
    *(uint4*)(g_xlo + drow) = *(const uint4*)&sh_lo[pos][chunk * 8];
}

// ---------------- prep: weights [o][c][k] -> [k][o][c] bf16 hi/lo ----------------
__global__ void prep_w(const float* __restrict__ w) {
    int idx = blockIdx.x * 256 + threadIdx.x;      // KE*O*C
    int c = idx & 63;
    int o = (idx >> 6) & 127;
    int k = idx >> 13;
    float v = w[(o * C_ + c) * KE_ + k];
    __nv_bfloat16 hi = __float2bfloat16(v);
    g_whi[idx] = hi;
    g_wlo[idx] = __float2bfloat16(v - __bfloat162float(hi));
}

// ---------------- main conv: warp-level mma.sync implicit GEMM, pipelined ------
__global__ __launch_bounds__(256, 1)
void conv_mma_kernel(float* __restrict__ out) {
    extern __shared__ char smem[];
    const uint32_t sbase = smem_u32(smem);
    const int tid = threadIdx.x;
    const int l = tid & 31, wid = tid >> 5;
    const int warpM = (wid >> 1) * 32;   // o offset: 0,32,64,96
    const int warpN = (wid & 1) * 64;    // w offset: 0,64
    const int h0 = blockIdx.x, b = blockIdx.y;

    // per-lane ldmatrix row/col pieces
    const int arow  = (l & 7) + ((l >> 3) & 1) * 8;   // A mats (0,0),(8,0),(0,8),(8,8)
    const int acolb = ((l >> 4) & 1) * 16;
    const int brow  = (l & 7) + ((l >> 4) & 1) * 8;   // B mats (n0,k0),(n0,k8),(n8,k0),(n8,k8)
    const int bcolb = ((l >> 3) & 1) * 16;

    // ---- prefetch x rows h0..h0+2 (padded coords), hi + lo, via cp.async ----
    for (int idx = tid; idx < 2 * XROWS * 8; idx += 256) {
        int s = idx >= XROWS * 8;
        int rem = idx - s * (XROWS * 8);
        int row = rem >> 3, chunk = rem & 7;
        int r = row / 130, wc = row - r * 130;
        const __nv_bfloat16* src = (s ? g_xlo : g_xhi)
            + ((size_t)(b * HP + h0 + r) * WP + wc) * C_ + chunk * 8;
        cp16(sbase + s * XTILE + sw(row * 128 + chunk * 16), src);
    }
    // ---- prefetch w tile 0 into buffer 0 ----
    {
        for (int idx = tid; idx < 2048; idx += 256) {
            int row = idx >> 3, chunk = idx & 7;      // row = s*128 + o
            int s = row >> 7, o = row & 127;
            const __nv_bfloat16* src = (s ? g_wlo : g_whi) + (size_t)o * C_ + chunk * 8;
            cp16(sbase + WS_OFF + sw(row * 128 + chunk * 16), src);
        }
    }
    CP_COMMIT();

    float acc[2][8][4];
    #pragma unroll
    for (int mt = 0; mt < 2; mt++)
        #pragma unroll
        for (int nt = 0; nt < 8; nt++)
            #pragma unroll
            for (int q = 0; q < 4; q++) acc[mt][nt][q] = 0.0f;

    #pragma unroll 1
    for (int t = 0; t < 9; t++) {                    // t = dh*3 + dw
        const int dh = t / 3, dw = t - dh * 3;
        const uint32_t wbuf = sbase + WS_OFF + (t & 1) * WTILE;

        if (t < 8) {
            // prefetch next w tile into the other buffer (freed by trailing sync)
            const uint32_t nbuf = sbase + WS_OFF + ((t + 1) & 1) * WTILE;
            for (int idx = tid; idx < 2048; idx += 256) {
                int row = idx >> 3, chunk = idx & 7;
                int s = row >> 7, o = row & 127;
                const __nv_bfloat16* src = (s ? g_wlo : g_whi)
                    + ((size_t)(t + 1) * O_ + o) * C_ + chunk * 8;
                cp16(nbuf + sw(row * 128 + chunk * 16), src);
            }
            CP_COMMIT();
            CP_WAIT(1);
        } else {
            CP_WAIT(0);
        }
        __syncthreads();

        #pragma unroll
        for (int ks = 0; ks < 4; ks++) {
            uint32_t ah[2][4], al[2][4], bb[4][4];
            #pragma unroll
            for (int mt = 0; mt < 2; mt++) {
                uint32_t rh = (uint32_t)(warpM + mt * 16 + arow);
                ldsm4(ah[mt], wbuf + sw(rh * 128 + ks * 32 + acolb));
                ldsm4(al[mt], wbuf + sw((rh + 128) * 128 + ks * 32 + acolb));
            }
            // B from x_hi
            #pragma unroll
            for (int np = 0; np < 4; np++) {
                uint32_t rn = (uint32_t)(dh * 130 + warpN + np * 16 + brow + dw);
                ldsm4(bb[np], sbase + sw(rn * 128 + ks * 32 + bcolb));
            }
            #pragma unroll
            for (int mt = 0; mt < 2; mt++)
                #pragma unroll
                for (int np = 0; np < 4; np++) {
                    mma16816(acc[mt][2 * np],     ah[mt], &bb[np][0]);  // w_hi * x_hi
                    mma16816(acc[mt][2 * np + 1], ah[mt], &bb[np][2]);
                    mma16816(acc[mt][2 * np],     al[mt], &bb[np][0]);  // w_lo * x_hi
                    mma16816(acc[mt][2 * np + 1], al[mt], &bb[np][2]);
                }
            // B from x_lo
            #pragma unroll
            for (int np = 0; np < 4; np++) {
                uint32_t rn = (uint32_t)(dh * 130 + warpN + np * 16 + brow + dw);
                ldsm4(bb[np], sbase + XTILE + sw(rn * 128 + ks * 32 + bcolb));
            }
            #pragma unroll
            for (int mt = 0; mt < 2; mt++)
                #pragma unroll
                for (int np = 0; np < 4; np++) {
                    mma16816(acc[mt][2 * np],     ah[mt], &bb[np][0]);  // w_hi * x_lo
                    mma16816(acc[mt][2 * np + 1], ah[mt], &bb[np][2]);
                }
        }
        __syncthreads();   // all reads of wbuf done before it is refilled at t+2
    }

    // ---- epilogue: fragment -> out[b][o][h0][w], float2 stores ----
    const int gid = l >> 2, tg = l & 3;
    #pragma unroll
    for (int mt = 0; mt < 2; mt++)
        #pragma unroll
        for (int half = 0; half < 2; half++) {
            int o = warpM + mt * 16 + gid + half * 8;
            float* dst = out + (((size_t)b * O_ + o) * H_ + h0) * W_ + warpN + 2 * tg;
            #pragma unroll
            for (int nt = 0; nt < 8; nt++) {
                float2 v = make_float2(acc[mt][nt][half * 2], acc[mt][nt][half * 2 + 1]);
                *(float2*)(dst + nt * 8) = v;
            }
        }
}

// ---------------- launch ----------------
extern "C" void kernel_launch(void* const* d_in, const int* in_sizes, int n_in,
                              void* d_out, int out_size) {
    const float* x = (const float*)d_in[0];
    const float* w = (const float*)d_in[1];
    float* out = (float*)d_out;

    cudaFuncSetAttribute(conv_mma_kernel, cudaFuncAttributeMaxDynamicSharedMemorySize,
                         SMEM_TOTAL);

    prep_x<<<B_ * H_ * 4, 256>>>(x);
    prep_w<<<(KE_ * O_ * C_) / 256, 256>>>(w);
    conv_mma_kernel<<<dim3(H_, B_), 256, SMEM_TOTAL>>>(out);
}

// round 7
// speedup vs baseline: 2.8114x; 1.0452x over previous
#include <cuda_runtime.h>
#include <cuda_bf16.h>
#include <cstdint>

// ---------------- problem constants ----------------
constexpr int B_ = 16, C_ = 64, H_ = 128, W_ = 128, O_ = 128, KE_ = 9;
constexpr int HP = H_ + 2, WP = W_ + 2;   // padded x copy dims

// ---------------- device scratch (zero-initialized; halo rows/cols stay 0) ----
__device__ __align__(16) __nv_bfloat16 g_xhi[(size_t)B_ * HP * WP * C_];
__device__ __align__(16) __nv_bfloat16 g_xlo[(size_t)B_ * HP * WP * C_];
__device__ __align__(16) __nv_bfloat16 g_whi[KE_ * O_ * C_];
__device__ __align__(16) __nv_bfloat16 g_wlo[KE_ * O_ * C_];

// ---------------- smem layout (bytes) ----------------
// x tiles: [s=hi/lo][4 padded rows][130 cols] rows of 128B (c=64 bf16), SW128
constexpr int XROWS = 4 * 130;                   // 520
constexpr int XTILE = XROWS * 128;               // 66560
constexpr int WS_OFF = 2 * XTILE;                // 133120
// w tile per (dh,dw): [s=hi/lo][o=128] rows of 128B = 32KB, double buffered
constexpr int WTILE = 256 * 128;                 // 32768
constexpr int SMEM_TOTAL = WS_OFF + 2 * WTILE;   // 198656

constexpr int NTHREADS = 512;                    // 16 warps, 4 per SMSP

__device__ __forceinline__ uint32_t sw(uint32_t off) { return off ^ ((off >> 3) & 0x70); }

__device__ __forceinline__ uint32_t smem_u32(const void* p) {
    uint32_t a;
    asm("{ .reg .u64 t; cvta.to.shared.u64 t, %1; cvt.u32.u64 %0, t; }" : "=r"(a) : "l"(p));
    return a;
}

__device__ __forceinline__ void cp16(uint32_t dst, const void* src) {
    asm volatile("cp.async.cg.shared.global [%0], [%1], 16;" :: "r"(dst), "l"(src));
}
#define CP_COMMIT() asm volatile("cp.async.commit_group;" ::: "memory")
#define CP_WAIT(n)  asm volatile("cp.async.wait_group %0;" :: "n"(n) : "memory")

__device__ __forceinline__ void ldsm4(uint32_t* r, uint32_t addr) {
    asm volatile("ldmatrix.sync.aligned.m8n8.x4.shared.b16 {%0,%1,%2,%3}, [%4];"
                 : "=r"(r[0]), "=r"(r[1]), "=r"(r[2]), "=r"(r[3]) : "r"(addr));
}

__device__ __forceinline__ void mma16816(float* d, const uint32_t* a, const uint32_t* b) {
    asm volatile(
        "mma.sync.aligned.m16n8k16.row.col.f32.bf16.bf16.f32 "
        "{%0,%1,%2,%3}, {%4,%5,%6,%7}, {%8,%9}, {%0,%1,%2,%3};"
        : "+f"(d[0]), "+f"(d[1]), "+f"(d[2]), "+f"(d[3])
        : "r"(a[0]), "r"(a[1]), "r"(a[2]), "r"(a[3]), "r"(b[0]), "r"(b[1]));
}

// ---------------- prep: x -> padded NHWC bf16 hi/lo, coalesced via smem transpose --
__global__ __launch_bounds__(256, 4) void prep_x(const float* __restrict__ x) {
    __shared__ __nv_bfloat16 sh_hi[32][72];
    __shared__ __nv_bfloat16 sh_lo[32][72];

    const int tid = threadIdx.x;
    const int wd = tid >> 5, l = tid & 31;
    const int blk = blockIdx.x;                  // b*H*4 + h*4 + wq
    const int wq = blk & 3;
    const int h  = (blk >> 2) & (H_ - 1);
    const int b  = blk >> 9;
    const int w0 = wq * 32;

    const float* src = x + (((size_t)b * C_ + wd) * H_ + h) * W_ + w0 + l;
    #pragma unroll
    for (int i = 0; i < 8; i++) {
        float v = src[(size_t)(i * 8) * H_ * W_];
        __nv_bfloat16 hi = __float2bfloat16(v);
        sh_hi[l][wd + i * 8] = hi;
        sh_lo[l][wd + i * 8] = __float2bfloat16(v - __bfloat162float(hi));
    }
    __syncthreads();

    const int pos = tid >> 3, chunk = tid & 7;
    size_t drow = ((size_t)(b * HP + h + 1) * WP + (w0 + pos + 1)) * C_ + chunk * 8;
    *(uint4*)(g_xhi + drow) = *(const uint4*)&sh_hi[pos][chunk * 8];
    *(uint4*)(g_xlo + drow) = *(const uint4*)&sh_lo[pos][chunk * 8];
}

// ---------------- prep: weights [o][c][k] -> [k][o][c] bf16 hi/lo ----------------
__global__ void prep_w(const float* __restrict__ w) {
    int idx = blockIdx.x * 256 + threadIdx.x;      // KE*O*C
    int c = idx & 63;
    int o = (idx >> 6) & 127;
    int k = idx >> 13;
    float v = w[(o * C_ + c) * KE_ + k];
    __nv_bfloat16 hi = __float2bfloat16(v);
    g_whi[idx] = hi;
    g_wlo[idx] = __float2bfloat16(v - __bfloat162float(hi));
}

// ---------------- main conv: 512-thread implicit GEMM, M=128 x N=256 -----------
__global__ __launch_bounds__(NTHREADS, 1)
void conv_mma_kernel(float* __restrict__ out) {
    extern __shared__ char smem[];
    const uint32_t sbase = smem_u32(smem);
    const int tid = threadIdx.x;
    const int l = tid & 31, wid = tid >> 5;
    const int warpM = (wid >> 2) * 32;     // o offset: 0,32,64,96
    const int warpN = (wid & 3) * 64;      // n offset over 256 (2 rows x 128)
    const int r_out = warpN >> 7;          // output row within pair
    const int wbase = warpN & 127;         // w column base
    const int h0 = blockIdx.x * 2, b = blockIdx.y;

    // per-lane ldmatrix row/col pieces
    const int arow  = (l & 7) + ((l >> 3) & 1) * 8;
    const int acolb = ((l >> 4) & 1) * 16;
    const int brow  = (l & 7) + ((l >> 4) & 1) * 8;
    const int bcolb = ((l >> 3) & 1) * 16;

    // ---- prefetch x padded rows h0..h0+3, hi + lo, via cp.async ----
    for (int idx = tid; idx < 2 * XROWS * 8; idx += NTHREADS) {
        int s = idx >= XROWS * 8;
        int rem = idx - s * (XROWS * 8);
        int row = rem >> 3, chunk = rem & 7;
        int r = row / 130, wc = row - r * 130;
        const __nv_bfloat16* src = (s ? g_xlo : g_xhi)
            + ((size_t)(b * HP + h0 + r) * WP + wc) * C_ + chunk * 8;
        cp16(sbase + s * XTILE + sw(row * 128 + chunk * 16), src);
    }
    // ---- prefetch w tile 0 into buffer 0 ----
    for (int idx = tid; idx < 2048; idx += NTHREADS) {
        int row = idx >> 3, chunk = idx & 7;
        int s = row >> 7, o = row & 127;
        const __nv_bfloat16* src = (s ? g_wlo : g_whi) + (size_t)o * C_ + chunk * 8;
        cp16(sbase + WS_OFF + sw(row * 128 + chunk * 16), src);
    }
    CP_COMMIT();

    float acc[2][8][4];
    #pragma unroll
    for (int mt = 0; mt < 2; mt++)
        #pragma unroll
        for (int nt = 0; nt < 8; nt++)
            #pragma unroll
            for (int q = 0; q < 4; q++) acc[mt][nt][q] = 0.0f;

    #pragma unroll 1
    for (int t = 0; t < 9; t++) {                    // t = dh*3 + dw
        const int dh = t / 3, dw = t - dh * 3;
        const uint32_t wbuf = sbase + WS_OFF + (t & 1) * WTILE;

        if (t < 8) {
            const uint32_t nbuf = sbase + WS_OFF + ((t + 1) & 1) * WTILE;
            for (int idx = tid; idx < 2048; idx += NTHREADS) {
                int row = idx >> 3, chunk = idx & 7;
                int s = row >> 7, o = row & 127;
                const __nv_bfloat16* src = (s ? g_wlo : g_whi)
                    + ((size_t)(t + 1) * O_ + o) * C_ + chunk * 8;
                cp16(nbuf + sw(row * 128 + chunk * 16), src);
            }
            CP_COMMIT();
            CP_WAIT(1);
        } else {
            CP_WAIT(0);
        }
        __syncthreads();

        const int browbase = (r_out + dh) * 130 + wbase + brow + dw;

        #pragma unroll
        for (int ks = 0; ks < 4; ks++) {
            uint32_t ah[2][4], al[2][4], bb[4][4];
            #pragma unroll
            for (int mt = 0; mt < 2; mt++) {
                uint32_t rh = (uint32_t)(warpM + mt * 16 + arow);
                ldsm4(ah[mt], wbuf + sw(rh * 128 + ks * 32 + acolb));
                ldsm4(al[mt], wbuf + sw((rh + 128) * 128 + ks * 32 + acolb));
            }
            // B from x_hi
            #pragma unroll
            for (int np = 0; np < 4; np++) {
                uint32_t rn = (uint32_t)(browbase + np * 16);
                ldsm4(bb[np], sbase + sw(rn * 128 + ks * 32 + bcolb));
            }
            #pragma unroll
            for (int mt = 0; mt < 2; mt++)
                #pragma unroll
                for (int np = 0; np < 4; np++) {
                    mma16816(acc[mt][2 * np],     ah[mt], &bb[np][0]);  // w_hi * x_hi
                    mma16816(acc[mt][2 * np + 1], ah[mt], &bb[np][2]);
                    mma16816(acc[mt][2 * np],     al[mt], &bb[np][0]);  // w_lo * x_hi
                    mma16816(acc[mt][2 * np + 1], al[mt], &bb[np][2]);
                }
            // B from x_lo
            #pragma unroll
            for (int np = 0; np < 4; np++) {
                uint32_t rn = (uint32_t)(browbase + np * 16);
                ldsm4(bb[np], sbase + XTILE + sw(rn * 128 + ks * 32 + bcolb));
            }
            #pragma unroll
            for (int mt = 0; mt < 2; mt++)
                #pragma unroll
                for (int np = 0; np < 4; np++) {
                    mma16816(acc[mt][2 * np],     ah[mt], &bb[np][0]);  // w_hi * x_lo
                    mma16816(acc[mt][2 * np + 1], ah[mt], &bb[np][2]);
                }
        }
        __syncthreads();   // all reads of wbuf done before refill at t+2
    }

    // ---- epilogue: fragment -> out[b][o][h][w], float2 stores ----
    const int gid = l >> 2, tg = l & 3;
    const int hh = h0 + r_out;
    #pragma unroll
    for (int mt = 0; mt < 2; mt++)
        #pragma unroll
        for (int half = 0; half < 2; half++) {
            int o = warpM + mt * 16 + gid + half * 8;
            float* dst = out + (((size_t)b * O_ + o) * H_ + hh) * W_ + wbase + 2 * tg;
            #pragma unroll
            for (int nt = 0; nt < 8; nt++) {
                float2 v = make_float2(acc[mt][nt][half * 2], acc[mt][nt][half * 2 + 1]);
                *(float2*)(dst + nt * 8) = v;
            }
        }
}

// ---------------- launch ----------------
extern "C" void kernel_launch(void* const* d_in, const int* in_sizes, int n_in,
                              void* d_out, int out_size) {
    const float* x = (const float*)d_in[0];
    const float* w = (const float*)d_in[1];
    float* out = (float*)d_out;

    cudaFuncSetAttribute(conv_mma_kernel, cudaFuncAttributeMaxDynamicSharedMemorySize,
                         SMEM_TOTAL);

    prep_x<<<B_ * H_ * 4, 256>>>(x);
    prep_w<<<(KE_ * O_ * C_) / 256, 256>>>(w);
    conv_mma_kernel<<<dim3(H_ / 2, B_), NTHREADS, SMEM_TOTAL>>>(out);
}

// round 8
// speedup vs baseline: 6.1356x; 2.1824x over previous
#include <cuda_runtime.h>
#include <cuda_bf16.h>
#include <cuda_fp16.h>
#include <cstdint>

// ---------------- problem constants ----------------
constexpr int B_ = 16, C_ = 64, H_ = 128, W_ = 128, O_ = 128, KE_ = 9;
constexpr int HP = H_ + 2, WP = W_ + 2;   // padded x copy dims

// ---------------- device scratch (zero-initialized; halo rows/cols stay 0) ----
__device__ __align__(16) __half g_xh[(size_t)B_ * HP * WP * C_];
__device__ __align__(16) __half g_wh[KE_ * O_ * C_];

// ---------------- smem layout (bytes) ----------------
// x tile: [3 padded rows][130 cols] rows of 128B (c=64 fp16), SW128
constexpr int XROWS = 3 * 130;                   // 390
constexpr int XTILE = XROWS * 128;               // 49920
constexpr int WS_OFF = XTILE;
// w tile per (dh,dw): [o=128] rows of 128B = 16KB, double buffered
constexpr int WTILE = 128 * 128;                 // 16384
constexpr int SMEM_TOTAL = WS_OFF + 2 * WTILE;   // 82688  -> 2 CTAs/SM

__device__ __forceinline__ uint32_t sw(uint32_t off) { return off ^ ((off >> 3) & 0x70); }

__device__ __forceinline__ uint32_t smem_u32(const void* p) {
    uint32_t a;
    asm("{ .reg .u64 t; cvta.to.shared.u64 t, %1; cvt.u32.u64 %0, t; }" : "=r"(a) : "l"(p));
    return a;
}

__device__ __forceinline__ void cp16(uint32_t dst, const void* src) {
    asm volatile("cp.async.cg.shared.global [%0], [%1], 16;" :: "r"(dst), "l"(src));
}
#define CP_COMMIT() asm volatile("cp.async.commit_group;" ::: "memory")
#define CP_WAIT(n)  asm volatile("cp.async.wait_group %0;" :: "n"(n) : "memory")

__device__ __forceinline__ void ldsm4(uint32_t* r, uint32_t addr) {
    asm volatile("ldmatrix.sync.aligned.m8n8.x4.shared.b16 {%0,%1,%2,%3}, [%4];"
                 : "=r"(r[0]), "=r"(r[1]), "=r"(r[2]), "=r"(r[3]) : "r"(addr));
}

__device__ __forceinline__ void mma16816(float* d, const uint32_t* a, const uint32_t* b) {
    asm volatile(
        "mma.sync.aligned.m16n8k16.row.col.f32.f16.f16.f32 "
        "{%0,%1,%2,%3}, {%4,%5,%6,%7}, {%8,%9}, {%0,%1,%2,%3};"
        : "+f"(d[0]), "+f"(d[1]), "+f"(d[2]), "+f"(d[3])
        : "r"(a[0]), "r"(a[1]), "r"(a[2]), "r"(a[3]), "r"(b[0]), "r"(b[1]));
}

// ---------------- prep: x -> padded NHWC fp16, coalesced via smem transpose ----
__global__ __launch_bounds__(256, 4) void prep_x(const float* __restrict__ x) {
    __shared__ __half sh[32][72];   // [w][c], stride 72 keeps 16B alignment

    const int tid = threadIdx.x;
    const int wd = tid >> 5, l = tid & 31;
    const int blk = blockIdx.x;                  // b*H*4 + h*4 + wq
    const int wq = blk & 3;
    const int h  = (blk >> 2) & (H_ - 1);
    const int b  = blk >> 9;
    const int w0 = wq * 32;

    const float* src = x + (((size_t)b * C_ + wd) * H_ + h) * W_ + w0 + l;
    #pragma unroll
    for (int i = 0; i < 8; i++)
        sh[l][wd + i * 8] = __float2half(src[(size_t)(i * 8) * H_ * W_]);
    __syncthreads();

    const int pos = tid >> 3, chunk = tid & 7;
    size_t drow = ((size_t)(b * HP + h + 1) * WP + (w0 + pos + 1)) * C_ + chunk * 8;
    *(uint4*)(g_xh + drow) = *(const uint4*)&sh[pos][chunk * 8];
}

// ---------------- prep: weights [o][c][k] -> [k][o][c] fp16 ----------------
__global__ void prep_w(const float* __restrict__ w) {
    int idx = blockIdx.x * 256 + threadIdx.x;      // KE*O*C
    int c = idx & 63;
    int o = (idx >> 6) & 127;
    int k = idx >> 13;
    g_wh[idx] = __float2half(w[(o * C_ + c) * KE_ + k]);
}

// ---------------- main conv: fp16 single-pass implicit GEMM, 2 CTAs/SM ---------
__global__ __launch_bounds__(256, 2)
void conv_mma_kernel(float* __restrict__ out) {
    extern __shared__ char smem[];
    const uint32_t sbase = smem_u32(smem);
    const int tid = threadIdx.x;
    const int l = tid & 31, wid = tid >> 5;
    const int warpM = (wid >> 1) * 32;   // o offset: 0,32,64,96
    const int warpN = (wid & 1) * 64;    // w offset: 0,64
    const int h0 = blockIdx.x, b = blockIdx.y;

    // per-lane ldmatrix row/col pieces
    const int arow  = (l & 7) + ((l >> 3) & 1) * 8;   // A mats (0,0),(8,0),(0,8),(8,8)
    const int acolb = ((l >> 4) & 1) * 16;
    const int brow  = (l & 7) + ((l >> 4) & 1) * 8;   // B mats (n0,k0),(n0,k8),(n8,k0),(n8,k8)
    const int bcolb = ((l >> 3) & 1) * 16;

    // ---- prefetch x rows h0..h0+2 (padded coords) via cp.async ----
    for (int idx = tid; idx < XROWS * 8; idx += 256) {
        int row = idx >> 3, chunk = idx & 7;
        int r = row / 130, wc = row - r * 130;
        const __half* src = g_xh + ((size_t)(b * HP + h0 + r) * WP + wc) * C_ + chunk * 8;
        cp16(sbase + sw(row * 128 + chunk * 16), src);
    }
    // ---- prefetch w tile 0 into buffer 0 ----
    for (int idx = tid; idx < 1024; idx += 256) {
        int o = idx >> 3, chunk = idx & 7;
        const __half* src = g_wh + (size_t)o * C_ + chunk * 8;
        cp16(sbase + WS_OFF + sw(o * 128 + chunk * 16), src);
    }
    CP_COMMIT();

    float acc[2][8][4];
    #pragma unroll
    for (int mt = 0; mt < 2; mt++)
        #pragma unroll
        for (int nt = 0; nt < 8; nt++)
            #pragma unroll
            for (int q = 0; q < 4; q++) acc[mt][nt][q] = 0.0f;

    #pragma unroll 1
    for (int t = 0; t < 9; t++) {                    // t = dh*3 + dw
        const int dh = t / 3, dw = t - dh * 3;
        const uint32_t wbuf = sbase + WS_OFF + (t & 1) * WTILE;

        if (t < 8) {
            const uint32_t nbuf = sbase + WS_OFF + ((t + 1) & 1) * WTILE;
            for (int idx = tid; idx < 1024; idx += 256) {
                int o = idx >> 3, chunk = idx & 7;
                const __half* src = g_wh + ((size_t)(t + 1) * O_ + o) * C_ + chunk * 8;
                cp16(nbuf + sw(o * 128 + chunk * 16), src);
            }
            CP_COMMIT();
            CP_WAIT(1);
        } else {
            CP_WAIT(0);
        }
        __syncthreads();

        const int browbase = dh * 130 + warpN + brow + dw;

        #pragma unroll
        for (int ks = 0; ks < 4; ks++) {
            uint32_t ah[2][4], bb[4][4];
            #pragma unroll
            for (int mt = 0; mt < 2; mt++) {
                uint32_t rh = (uint32_t)(warpM + mt * 16 + arow);
                ldsm4(ah[mt], wbuf + sw(rh * 128 + ks * 32 + acolb));
            }
            #pragma unroll
            for (int np = 0; np < 4; np++) {
                uint32_t rn = (uint32_t)(browbase + np * 16);
                ldsm4(bb[np], sbase + sw(rn * 128 + ks * 32 + bcolb));
            }
            #pragma unroll
            for (int mt = 0; mt < 2; mt++)
                #pragma unroll
                for (int np = 0; np < 4; np++) {
                    mma16816(acc[mt][2 * np],     ah[mt], &bb[np][0]);
                    mma16816(acc[mt][2 * np + 1], ah[mt], &bb[np][2]);
                }
        }
        __syncthreads();   // all reads of wbuf done before refill at t+2
    }

    // ---- epilogue: fragment -> out[b][o][h0][w], float2 stores ----
    const int gid = l >> 2, tg = l & 3;
    #pragma unroll
    for (int mt = 0; mt < 2; mt++)
        #pragma unroll
        for (int half = 0; half < 2; half++) {
            int o = warpM + mt * 16 + gid + half * 8;
            float* dst = out + (((size_t)b * O_ + o) * H_ + h0) * W_ + warpN + 2 * tg;
            #pragma unroll
            for (int nt = 0; nt < 8; nt++) {
                float2 v = make_float2(acc[mt][nt][half * 2], acc[mt][nt][half * 2 + 1]);
                *(float2*)(dst + nt * 8) = v;
            }
        }
}

// ---------------- launch ----------------
extern "C" void kernel_launch(void* const* d_in, const int* in_sizes, int n_in,
                              void* d_out, int out_size) {
    const float* x = (const float*)d_in[0];
    const float* w = (const float*)d_in[1];
    float* out = (float*)d_out;

    cudaFuncSetAttribute(conv_mma_kernel, cudaFuncAttributeMaxDynamicSharedMemorySize,
                         SMEM_TOTAL);

    prep_x<<<B_ * H_ * 4, 256>>>(x);
    prep_w<<<(KE_ * O_ * C_) / 256, 256>>>(w);
    conv_mma_kernel<<<dim3(H_, B_), 256, SMEM_TOTAL>>>(out);
}

// round 9
// speedup vs baseline: 7.1837x; 1.1708x over previous
#include <cuda_runtime.h>
#include <cuda_fp16.h>
#include <cstdint>

// ---------------- problem constants ----------------
constexpr int B_ = 16, C_ = 64, H_ = 128, W_ = 128, O_ = 128, KE_ = 9;
constexpr int HP = H_ + 2, WP = W_ + 2;   // padded x copy dims

// ---------------- device scratch (zero-initialized; halo stays 0) ----------------
__device__ __align__(16) __half g_xh[(size_t)B_ * HP * WP * C_];
// w in MMA-fragment-major layout: [tap(9)][mblock(8)][ks(4)][lane(32)] -> uint4
__device__ __align__(16) uint4 g_wfrag[KE_ * 8 * 4 * 32];

// ---------------- smem layout (bytes): x tile only ----------------
// x tile: [3 padded rows][130 cols] rows of 128B (c=64 fp16), SW128
constexpr int XROWS = 3 * 130;                   // 390
constexpr int SMEM_TOTAL = XROWS * 128;          // 49920

__device__ __forceinline__ uint32_t sw(uint32_t off) { return off ^ ((off >> 3) & 0x70); }

__device__ __forceinline__ uint32_t smem_u32(const void* p) {
    uint32_t a;
    asm("{ .reg .u64 t; cvta.to.shared.u64 t, %1; cvt.u32.u64 %0, t; }" : "=r"(a) : "l"(p));
    return a;
}

__device__ __forceinline__ void cp16(uint32_t dst, const void* src) {
    asm volatile("cp.async.cg.shared.global [%0], [%1], 16;" :: "r"(dst), "l"(src));
}
#define CP_COMMIT() asm volatile("cp.async.commit_group;" ::: "memory")
#define CP_WAIT0()  asm volatile("cp.async.wait_group 0;" ::: "memory")

__device__ __forceinline__ void ldsm4(uint32_t* r, uint32_t addr) {
    asm volatile("ldmatrix.sync.aligned.m8n8.x4.shared.b16 {%0,%1,%2,%3}, [%4];"
                 : "=r"(r[0]), "=r"(r[1]), "=r"(r[2]), "=r"(r[3]) : "r"(addr));
}

__device__ __forceinline__ void mma16816(float* d, const uint32_t* a, const uint32_t* b) {
    asm volatile(
        "mma.sync.aligned.m16n8k16.row.col.f32.f16.f16.f32 "
        "{%0,%1,%2,%3}, {%4,%5,%6,%7}, {%8,%9}, {%0,%1,%2,%3};"
        : "+f"(d[0]), "+f"(d[1]), "+f"(d[2]), "+f"(d[3])
        : "r"(a[0]), "r"(a[1]), "r"(a[2]), "r"(a[3]), "r"(b[0]), "r"(b[1]));
}

// ---------------- fused prep: x transpose + w fragment packing ----------------
// blocks [0, B*H*4): x path.  blocks [B*H*4, B*H*4+36): w path.
constexpr int XBLOCKS = B_ * H_ * 4;   // 8192

__global__ __launch_bounds__(256, 4) void prep_kernel(const float* __restrict__ x,
                                                      const float* __restrict__ w) {
    if (blockIdx.x >= XBLOCKS) {
        // ---- w path: pack m16n8k16 A fragments ----
        int idx = (blockIdx.x - XBLOCKS) * 256 + threadIdx.x;   // 9216 total
        if (idx < KE_ * 1024) {
            int l  = idx & 31;
            int ks = (idx >> 5) & 3;
            int mb = (idx >> 7) & 7;
            int k  = idx >> 10;
            int gid = l >> 2, tg2 = (l & 3) * 2;
            int o0 = mb * 16 + gid;
            int c0 = ks * 16 + tg2;
            // original layout: w[(o * C + c) * KE + k]
            auto wv = [&](int o, int c) { return __float2half(w[(o * C_ + c) * KE_ + k]); };
            __align__(16) __half h[8];
            h[0] = wv(o0, c0);         h[1] = wv(o0, c0 + 1);
            h[2] = wv(o0 + 8, c0);     h[3] = wv(o0 + 8, c0 + 1);
            h[4] = wv(o0, c0 + 8);     h[5] = wv(o0, c0 + 9);
            h[6] = wv(o0 + 8, c0 + 8); h[7] = wv(o0 + 8, c0 + 9);
            g_wfrag[idx] = *(const uint4*)h;
        }
        return;
    }

    // ---- x path: padded NHWC fp16 via smem transpose ----
    __shared__ __half sh[32][72];
    const int tid = threadIdx.x;
    const int wd = tid >> 5, l = tid & 31;
    const int blk = blockIdx.x;                  // b*H*4 + h*4 + wq
    const int wq = blk & 3;
    const int h  = (blk >> 2) & (H_ - 1);
    const int b  = blk >> 9;
    const int w0 = wq * 32;

    const float* src = x + (((size_t)b * C_ + wd) * H_ + h) * W_ + w0 + l;
    #pragma unroll
    for (int i = 0; i < 8; i++)
        sh[l][wd + i * 8] = __float2half(src[(size_t)(i * 8) * H_ * W_]);
    __syncthreads();

    const int pos = tid >> 3, chunk = tid & 7;
    size_t drow = ((size_t)(b * HP + h + 1) * WP + (w0 + pos + 1)) * C_ + chunk * 8;
    *(uint4*)(g_xh + drow) = *(const uint4*)&sh[pos][chunk * 8];
}

// ---------------- main conv: barrier-free mainloop, w frags via LDG/L1 ---------
__global__ __launch_bounds__(256, 2)
void conv_mma_kernel(float* __restrict__ out) {
    extern __shared__ char smem[];
    const uint32_t sbase = smem_u32(smem);
    const int tid = threadIdx.x;
    const int l = tid & 31, wid = tid >> 5;
    const int warpM = (wid >> 1) * 32;   // o offset: 0,32,64,96
    const int warpN = (wid & 1) * 64;    // w offset: 0,64
    const int h0 = blockIdx.x, b = blockIdx.y;

    // per-lane ldmatrix pieces for B
    const int brow  = (l & 7) + ((l >> 4) & 1) * 8;
    const int bcolb = ((l >> 3) & 1) * 16;

    // ---- prologue: stage x rows h0..h0+2 (padded coords) via cp.async ----
    for (int idx = tid; idx < XROWS * 8; idx += 256) {
        int row = idx >> 3, chunk = idx & 7;
        int r = row / 130, wc = row - r * 130;
        const __half* src = g_xh + ((size_t)(b * HP + h0 + r) * WP + wc) * C_ + chunk * 8;
        cp16(sbase + sw(row * 128 + chunk * 16), src);
    }
    CP_COMMIT();

    float acc[2][8][4];
    #pragma unroll
    for (int mt = 0; mt < 2; mt++)
        #pragma unroll
        for (int nt = 0; nt < 8; nt++)
            #pragma unroll
            for (int q = 0; q < 4; q++) acc[mt][nt][q] = 0.0f;

    // base index into g_wfrag for this warp: [t][mb = warpM/16 + mt][ks][l]
    const uint4* wf = g_wfrag + (warpM >> 4) * 128 + l;

    CP_WAIT0();
    __syncthreads();   // x tile ready; the ONLY barrier in the kernel

    #pragma unroll
    for (int t = 0; t < 9; t++) {                    // t = dh*3 + dw
        const int dh = t / 3, dw = t - dh * 3;
        const int browbase = dh * 130 + warpN + brow + dw;
        const uint4* wft = wf + t * 1024;

        #pragma unroll
        for (int ks = 0; ks < 4; ks++) {
            uint4 af[2];
            #pragma unroll
            for (int mt = 0; mt < 2; mt++)
                af[mt] = wft[mt * 128 + ks * 32];    // LDG.128, L1-resident
            uint32_t bb[4][4];
            #pragma unroll
            for (int np = 0; np < 4; np++) {
                uint32_t rn = (uint32_t)(browbase + np * 16);
                ldsm4(bb[np], sbase + sw(rn * 128 + ks * 32 + bcolb));
            }
            #pragma unroll
            for (int mt = 0; mt < 2; mt++)
                #pragma unroll
                for (int np = 0; np < 4; np++) {
                    mma16816(acc[mt][2 * np],     (const uint32_t*)&af[mt], &bb[np][0]);
                    mma16816(acc[mt][2 * np + 1], (const uint32_t*)&af[mt], &bb[np][2]);
                }
        }
    }

    // ---- epilogue: fragment -> out[b][o][h0][w], float2 stores ----
    const int gid = l >> 2, tg = l & 3;
    #pragma unroll
    for (int mt = 0; mt < 2; mt++)
        #pragma unroll
        for (int half = 0; half < 2; half++) {
            int o = warpM + mt * 16 + gid + half * 8;
            float* dst = out + (((size_t)b * O_ + o) * H_ + h0) * W_ + warpN + 2 * tg;
            #pragma unroll
            for (int nt = 0; nt < 8; nt++) {
                float2 v = make_float2(acc[mt][nt][half * 2], acc[mt][nt][half * 2 + 1]);
                *(float2*)(dst + nt * 8) = v;
            }
        }
}

// ---------------- launch ----------------
extern "C" void kernel_launch(void* const* d_in, const int* in_sizes, int n_in,
                              void* d_out, int out_size) {
    const float* x = (const float*)d_in[0];
    const float* w = (const float*)d_in[1];
    float* out = (float*)d_out;

    cudaFuncSetAttribute(conv_mma_kernel, cudaFuncAttributeMaxDynamicSharedMemorySize,
                         SMEM_TOTAL);

    prep_kernel<<<XBLOCKS + 36, 256>>>(x, w);
    conv_mma_kernel<<<dim3(H_, B_), 256, SMEM_TOTAL>>>(out);
}

// round 10
// speedup vs baseline: 7.9909x; 1.1124x over previous
#include <cuda_runtime.h>
#include <cuda_fp16.h>
#include <cstdint>

// ---------------- problem constants ----------------
constexpr int B_ = 16, C_ = 64, H_ = 128, W_ = 128, O_ = 128, KE_ = 9;

// ---------------- device scratch ----------------
// w in MMA-fragment-major layout: [tap(9)][mblock(8)][ks(4)][lane(32)] -> uint4
__device__ __align__(16) uint4 g_wfrag[KE_ * 8 * 4 * 32];

// ---------------- smem layout (bytes): x tile only ----------------
// x tile: [3 padded rows][130 cols] rows of 128B (c=64 fp16), SW128
constexpr int XROWS = 3 * 130;                   // 390
constexpr int SMEM_TOTAL = XROWS * 128;          // 49920

__device__ __forceinline__ uint32_t sw(uint32_t off) { return off ^ ((off >> 3) & 0x70); }

__device__ __forceinline__ uint32_t smem_u32(const void* p) {
    uint32_t a;
    asm("{ .reg .u64 t; cvta.to.shared.u64 t, %1; cvt.u32.u64 %0, t; }" : "=r"(a) : "l"(p));
    return a;
}

__device__ __forceinline__ void ldsm4(uint32_t* r, uint32_t addr) {
    asm volatile("ldmatrix.sync.aligned.m8n8.x4.shared.b16 {%0,%1,%2,%3}, [%4];"
                 : "=r"(r[0]), "=r"(r[1]), "=r"(r[2]), "=r"(r[3]) : "r"(addr));
}

__device__ __forceinline__ void mma16816(float* d, const uint32_t* a, const uint32_t* b) {
    asm volatile(
        "mma.sync.aligned.m16n8k16.row.col.f32.f16.f16.f32 "
        "{%0,%1,%2,%3}, {%4,%5,%6,%7}, {%8,%9}, {%0,%1,%2,%3};"
        : "+f"(d[0]), "+f"(d[1]), "+f"(d[2]), "+f"(d[3])
        : "r"(a[0]), "r"(a[1]), "r"(a[2]), "r"(a[3]), "r"(b[0]), "r"(b[1]));
}

// ---------------- prep: w -> m16n8k16 A fragments (tiny, only serial work) ------
__global__ __launch_bounds__(256) void prep_w(const float* __restrict__ w) {
    int idx = blockIdx.x * 256 + threadIdx.x;   // KE*1024 = 9216 total
    if (idx < KE_ * 1024) {
        int l  = idx & 31;
        int ks = (idx >> 5) & 3;
        int mb = (idx >> 7) & 7;
        int k  = idx >> 10;
        int gid = l >> 2, tg2 = (l & 3) * 2;
        int o0 = mb * 16 + gid;
        int c0 = ks * 16 + tg2;
        auto wv = [&](int o, int c) { return __float2half(w[(o * C_ + c) * KE_ + k]); };
        __align__(16) __half h[8];
        h[0] = wv(o0, c0);         h[1] = wv(o0, c0 + 1);
        h[2] = wv(o0 + 8, c0);     h[3] = wv(o0 + 8, c0 + 1);
        h[4] = wv(o0, c0 + 8);     h[5] = wv(o0, c0 + 9);
        h[6] = wv(o0 + 8, c0 + 8); h[7] = wv(o0 + 8, c0 + 9);
        g_wfrag[idx] = *(const uint4*)h;
    }
}

// ---------------- main conv: direct-NCHW staging, barrier-free mainloop ---------
__global__ __launch_bounds__(256, 2)
void conv_mma_kernel(const float* __restrict__ x, float* __restrict__ out) {
    extern __shared__ char smem[];
    const uint32_t sbase = smem_u32(smem);
    const int tid = threadIdx.x;
    const int l = tid & 31, wid = tid >> 5;
    const int warpM = (wid >> 1) * 32;   // o offset: 0,32,64,96
    const int warpN = (wid & 1) * 64;    // w offset: 0,64
    const int h0 = blockIdx.x, b = blockIdx.y;

    // per-lane ldmatrix pieces for B
    const int brow  = (l & 7) + ((l >> 4) & 1) * 8;
    const int bcolb = ((l >> 3) & 1) * 16;

    // ---- prologue: convert+transpose x rows h0-1..h0+1 straight from NCHW fp32 --
    // row = r*130 + wp; thread owns whole 128B c-row. Lanes = consecutive wp ->
    // coalesced LDG.32 per c; swizzle spreads STS.128 across column phases.
    #pragma unroll
    for (int it = 0; it < 2; it++) {
        int row = tid + it * 256;
        if (row < XROWS) {
            int r = row / 130, wp = row - r * 130;
            int gh = h0 - 1 + r, gw = wp - 1;
            bool valid = ((unsigned)gh < (unsigned)H_) && ((unsigned)gw < (unsigned)W_);
            const float* src = x + (((size_t)b * C_) * H_ + gh) * (size_t)W_ + gw;
            const size_t cstride = (size_t)H_ * W_;
            uint32_t pk[32];
            #pragma unroll
            for (int j = 0; j < 32; j++) {
                float v0 = valid ? src[(2 * j) * cstride] : 0.0f;
                float v1 = valid ? src[(2 * j + 1) * cstride] : 0.0f;
                __half2 hh = __floats2half2_rn(v0, v1);
                pk[j] = *(const uint32_t*)&hh;
            }
            #pragma unroll
            for (int ch = 0; ch < 8; ch++) {
                uint4 v = make_uint4(pk[4 * ch], pk[4 * ch + 1], pk[4 * ch + 2], pk[4 * ch + 3]);
                *(uint4*)(smem + sw(row * 128 + ch * 16)) = v;
            }
        }
    }

    float acc[2][8][4];
    #pragma unroll
    for (int mt = 0; mt < 2; mt++)
        #pragma unroll
        for (int nt = 0; nt < 8; nt++)
            #pragma unroll
            for (int q = 0; q < 4; q++) acc[mt][nt][q] = 0.0f;

    // base index into g_wfrag for this warp: [t][mb = warpM/16 + mt][ks][l]
    const uint4* wf = g_wfrag + (warpM >> 4) * 128 + l;

    __syncthreads();   // x tile ready; the ONLY barrier in the kernel

    #pragma unroll
    for (int t = 0; t < 9; t++) {                    // t = dh*3 + dw
        const int dh = t / 3, dw = t - dh * 3;
        const int browbase = dh * 130 + warpN + brow + dw;
        const uint4* wft = wf + t * 1024;

        #pragma unroll
        for (int ks = 0; ks < 4; ks++) {
            uint4 af[2];
            #pragma unroll
            for (int mt = 0; mt < 2; mt++)
                af[mt] = wft[mt * 128 + ks * 32];    // LDG.128, L1/L2-resident
            uint32_t bb[4][4];
            #pragma unroll
            for (int np = 0; np < 4; np++) {
                uint32_t rn = (uint32_t)(browbase + np * 16);
                ldsm4(bb[np], sbase + sw(rn * 128 + ks * 32 + bcolb));
            }
            #pragma unroll
            for (int mt = 0; mt < 2; mt++)
                #pragma unroll
                for (int np = 0; np < 4; np++) {
                    mma16816(acc[mt][2 * np],     (const uint32_t*)&af[mt], &bb[np][0]);
                    mma16816(acc[mt][2 * np + 1], (const uint32_t*)&af[mt], &bb[np][2]);
                }
        }
    }

    // ---- epilogue: fragment -> out[b][o][h0][w], float2 stores ----
    const int gid = l >> 2, tg = l & 3;
    #pragma unroll
    for (int mt = 0; mt < 2; mt++)
        #pragma unroll
        for (int half = 0; half < 2; half++) {
            int o = warpM + mt * 16 + gid + half * 8;
            float* dst = out + (((size_t)b * O_ + o) * H_ + h0) * W_ + warpN + 2 * tg;
            #pragma unroll
            for (int nt = 0; nt < 8; nt++) {
                float2 v = make_float2(acc[mt][nt][half * 2], acc[mt][nt][half * 2 + 1]);
                *(float2*)(dst + nt * 8) = v;
            }
        }
}

// ---------------- launch ----------------
extern "C" void kernel_launch(void* const* d_in, const int* in_sizes, int n_in,
                              void* d_out, int out_size) {
    const float* x = (const float*)d_in[0];
    const float* w = (const float*)d_in[1];
    float* out = (float*)d_out;

    cudaFuncSetAttribute(conv_mma_kernel, cudaFuncAttributeMaxDynamicSharedMemorySize,
                         SMEM_TOTAL);

    prep_w<<<36, 256>>>(w);
    conv_mma_kernel<<<dim3(H_, B_), 256, SMEM_TOTAL>>>(x, out);
}